// round 16
// baseline (speedup 1.0000x reference)
#include <cuda_runtime.h>
#include <cuda_fp16.h>
#include <math.h>
#include <stdint.h>

#define BB 256
#define TT 2048
#define EE 128
#define OCC 128
#define VOC1 50001
#define NTILES 4096          // BB * TT / 128
#define GRID 148
#define STH 136              // half-stride of E/W tiles (68 uint32) -> conflict-free frags
#define STU (STH / 2)        // 68

// SMEM byte offsets
#define OFF_E0   0                         // E tile buf0: 128 x 136 halves = 34816
#define OFF_E1   34816
#define OFF_W    69632                     // W tile: 136 x 136 halves = 36992
#define OFF_Q    106624                    // q: 132 rows x 8 floats = 4224
#define OFF_SIG  110848                    // 128 floats
#define OFF_ATT  111360                    // 5 x 128 floats (halo path)
#define SMEM_DYN 113920

__device__ float g_part[NTILES * 2 * OCC];                 // 4 MB partial maxes
__device__ __align__(16) __half g_emb16[VOC1 * EE];        // 12.8 MB fp16 table

static __device__ __forceinline__ uint32_t smem_u32(const void* p) {
    uint32_t a;
    asm("{ .reg .u64 t; cvta.to.shared.u64 t, %1; cvt.u32.u64 %0, t; }" : "=r"(a) : "l"(p));
    return a;
}
static __device__ __forceinline__ void cpasync16(uint32_t dst, const void* src) {
    asm volatile("cp.async.cg.shared.global [%0], [%1], 16;" :: "r"(dst), "l"(src));
}
static __device__ __forceinline__ void mma16(float* c,
                                             uint32_t a0, uint32_t a1, uint32_t a2, uint32_t a3,
                                             uint32_t b0, uint32_t b1) {
    asm volatile(
        "mma.sync.aligned.m16n8k16.row.col.f32.f16.f16.f32 "
        "{%0,%1,%2,%3}, {%4,%5,%6,%7}, {%8,%9}, {%0,%1,%2,%3};"
        : "+f"(c[0]), "+f"(c[1]), "+f"(c[2]), "+f"(c[3])
        : "r"(a0), "r"(a1), "r"(a2), "r"(a3), "r"(b0), "r"(b1));
}

// ---- one-shot fp32 -> fp16 table conversion (runs every replay; deterministic) ----
__global__ void emb_conv(const float* __restrict__ emb) {
    const int i = blockIdx.x * blockDim.x + threadIdx.x;   // 8 halves per thread
    if (i >= (VOC1 * EE) / 8) return;
    const float4* s = (const float4*)emb + 2 * i;
    float4 v0 = s[0], v1 = s[1];
    __half2 h0 = __floats2half2_rn(v0.x, v0.y);
    __half2 h1 = __floats2half2_rn(v0.z, v0.w);
    __half2 h2 = __floats2half2_rn(v1.x, v1.y);
    __half2 h3 = __floats2half2_rn(v1.z, v1.w);
    uint4 u;
    u.x = *(uint32_t*)&h0; u.y = *(uint32_t*)&h1;
    u.z = *(uint32_t*)&h2; u.w = *(uint32_t*)&h3;
    ((uint4*)g_emb16)[i] = u;
}

__global__ void __launch_bounds__(256, 1) la_main(
    const int* __restrict__ x, const float* __restrict__ attw,
    const float* __restrict__ attb, const float* __restrict__ cnnw)
{
    extern __shared__ char sm[];
    float* smQ   = (float*)(sm + OFF_Q);     // [u][8], u = 0..131
    float* smSIG = (float*)(sm + OFF_SIG);
    float* smATT = (float*)(sm + OFF_ATT);
    const uint32_t smb = smem_u32(sm);

    const int tid  = threadIdx.x;
    const int lane = tid & 31;
    const int w    = tid >> 5;
    const int wo   = w & 3;          // o-quadrant
    const int mh   = w >> 2;         // t-half
    const int l4   = lane >> 2;
    const int lm   = lane & 3;
    const int r    = tid >> 1;       // row owned in gather (2 threads/row)
    const int h    = tid & 1;        // 64-half segment

    // ---- one-time: W fp16 tile (rows 0..127 = cnn_w, 128..132 = att_w, 133..135 = 0) ----
    {
        const float4* src = (const float4*)(cnnw + r * EE + h * 64);
        uint2* dst = (uint2*)(sm + OFF_W + (r * STH + h * 64) * 2);
        #pragma unroll
        for (int i = 0; i < 16; i++) {
            float4 v = src[i];
            __half2 p01 = __floats2half2_rn(v.x, v.y);
            __half2 p23 = __floats2half2_rn(v.z, v.w);
            uint2 u; u.x = *(uint32_t*)&p01; u.y = *(uint32_t*)&p23;
            dst[i] = u;
        }
    }
    if (tid < 64) {  // 8 extra rows, 8 threads/row, 16 halves each
        const int j = tid >> 3, seg = tid & 7;
        uint2* dst = (uint2*)(sm + OFF_W + ((128 + j) * STH + seg * 16) * 2);
        #pragma unroll
        for (int i = 0; i < 4; i++) {
            float4 v = (j < 5) ? *(const float4*)(attw + j * EE + seg * 16 + 4 * i)
                               : make_float4(0.f, 0.f, 0.f, 0.f);
            __half2 p01 = __floats2half2_rn(v.x, v.y);
            __half2 p23 = __floats2half2_rn(v.z, v.w);
            uint2 u; u.x = *(uint32_t*)&p01; u.y = *(uint32_t*)&p23;
            dst[i] = u;
        }
    }
    for (int i = tid; i < 5 * EE; i += 256) smATT[i] = attw[i];
    const float bias = attb[0];
    __syncthreads();

    const uint32_t* hW = (const uint32_t*)(sm + OFF_W);
    const int aBase = (mh * 64 + l4) * STU + lm;
    const int bBase = (wo * 32 + l4) * STU + lm;
    const int bqBase = (128 + l4) * STU + lm;          // q columns (n = 128..135)
    const uint32_t eDst = (uint32_t)((r * STH + h * 64) * 2);

    // ---- prologue prefetch: first tile -> E0 ----
    {
        const int tile = blockIdx.x;
        const int tok = x[(tile >> 4) * TT + ((tile & 15) << 7) + r];
        const __half* src = g_emb16 + (size_t)tok * EE + h * 64;
        #pragma unroll
        for (int i = 0; i < 8; i++) cpasync16(smb + OFF_E0 + eDst + 16 * i, src + 8 * i);
    }
    asm volatile("cp.async.commit_group;" ::: "memory");

    int buf = 0;
    for (int tile = blockIdx.x; tile < NTILES; tile += GRID) {
        const int b  = tile >> 4;
        const int tb = (tile & 15) << 7;
        const bool has_next = (tile + GRID) < NTILES;

        if (has_next) {
            const int nt = tile + GRID;
            const int tok = x[(nt >> 4) * TT + ((nt & 15) << 7) + r];
            const __half* src = g_emb16 + (size_t)tok * EE + h * 64;
            const uint32_t d = smb + (buf ? OFF_E0 : OFF_E1) + eDst;
            #pragma unroll
            for (int i = 0; i < 8; i++) cpasync16(d + 16 * i, src + 8 * i);
            asm volatile("cp.async.commit_group;" ::: "memory");
            asm volatile("cp.async.wait_group 1;" ::: "memory");
        } else {
            asm volatile("cp.async.wait_group 0;" ::: "memory");
        }
        __syncthreads();   // E[buf] visible

        // ---- halo q (warp 1): rows t-2, t-1, t+128, t+129 -> smQ u = 0,1,130,131 ----
        if (w == 1) {
            const int hh = lane >> 3, seg = lane & 7;
            const int tg = (hh < 2) ? (tb - 2 + hh) : (tb + 126 + hh);
            float vk[5] = {0.f, 0.f, 0.f, 0.f, 0.f};
            if (tg >= 0 && tg < TT) {
                const int tok = x[b * TT + tg];
                const uint4* src = (const uint4*)(g_emb16 + (size_t)tok * EE + seg * 16);
                const float* aw = smATT + seg * 16;
                #pragma unroll
                for (int c8 = 0; c8 < 2; c8++) {
                    uint4 u = src[c8];
                    float f[8];
                    f[0] = __low2float(*(__half2*)&u.x);  f[1] = __high2float(*(__half2*)&u.x);
                    f[2] = __low2float(*(__half2*)&u.y);  f[3] = __high2float(*(__half2*)&u.y);
                    f[4] = __low2float(*(__half2*)&u.z);  f[5] = __high2float(*(__half2*)&u.z);
                    f[6] = __low2float(*(__half2*)&u.w);  f[7] = __high2float(*(__half2*)&u.w);
                    #pragma unroll
                    for (int e = 0; e < 8; e++)
                        #pragma unroll
                        for (int k = 0; k < 5; k++)
                            vk[k] += f[e] * aw[k * EE + c8 * 8 + e];
                }
            }
            #pragma unroll
            for (int k = 0; k < 5; k++) {
                vk[k] += __shfl_xor_sync(0xffffffffu, vk[k], 1);
                vk[k] += __shfl_xor_sync(0xffffffffu, vk[k], 2);
                vk[k] += __shfl_xor_sync(0xffffffffu, vk[k], 4);
            }
            if (seg == 0) {
                const int u = (hh < 2) ? hh : hh + 128;
                #pragma unroll
                for (int k = 0; k < 5; k++) smQ[u * 8 + k] = vk[k];
            }
        }

        // ---- fp16 k-loop: 64t x 32o per warp (+ q columns on wo==3) ----
        const uint32_t* hE = (const uint32_t*)(sm + (buf ? OFF_E1 : OFF_E0));
        float acc[4][4][4];
        float accq[4][4];
        #pragma unroll
        for (int mb = 0; mb < 4; mb++) {
            #pragma unroll
            for (int nb = 0; nb < 4; nb++)
                #pragma unroll
                for (int j = 0; j < 4; j++) acc[mb][nb][j] = 0.f;
            #pragma unroll
            for (int j = 0; j < 4; j++) accq[mb][j] = 0.f;
        }

        #pragma unroll
        for (int kb = 0; kb < 8; kb++) {
            const int kc = kb * 8;
            uint32_t b0[4], b1[4], bq0 = 0, bq1 = 0;
            #pragma unroll
            for (int nb = 0; nb < 4; nb++) {
                b0[nb] = hW[bBase + nb * 8 * STU + kc];
                b1[nb] = hW[bBase + nb * 8 * STU + kc + 4];
            }
            if (wo == 3) {
                bq0 = hW[bqBase + kc];
                bq1 = hW[bqBase + kc + 4];
            }
            #pragma unroll
            for (int mb = 0; mb < 4; mb++) {
                const int ao = aBase + mb * 16 * STU + kc;
                const uint32_t a0 = hE[ao];
                const uint32_t a1 = hE[ao + 8 * STU];
                const uint32_t a2 = hE[ao + 4];
                const uint32_t a3 = hE[ao + 8 * STU + 4];
                #pragma unroll
                for (int nb = 0; nb < 4; nb++)
                    mma16(acc[mb][nb], a0, a1, a2, a3, b0[nb], b1[nb]);
                if (wo == 3)
                    mma16(accq[mb], a0, a1, a2, a3, bq0, bq1);
            }
        }

        // ---- wo==3: scatter q fragments (cols j = 2lm, 2lm+1; keep j < 5) ----
        if (wo == 3 && lm < 3) {
            #pragma unroll
            for (int mb = 0; mb < 4; mb++) {
                const int u0 = mh * 64 + mb * 16 + l4 + 2;
                const int j0 = 2 * lm;
                smQ[u0 * 8 + j0] = accq[mb][0];
                smQ[(u0 + 8) * 8 + j0] = accq[mb][2];
                if (j0 + 1 < 5) {
                    smQ[u0 * 8 + j0 + 1] = accq[mb][1];
                    smQ[(u0 + 8) * 8 + j0 + 1] = accq[mb][3];
                }
            }
        }
        __syncthreads();   // q complete; E[buf] reads done

        // ---- sigmoid: s[t] = sum_k q[t+k][k] ----
        if (tid < 128) {
            float s = smQ[tid * 8]
                    + smQ[(tid + 1) * 8 + 1]
                    + smQ[(tid + 2) * 8 + 2]
                    + smQ[(tid + 3) * 8 + 3]
                    + smQ[(tid + 4) * 8 + 4];
            smSIG[tid] = 1.f / (1.f + __expf(-(s + bias)));
        }
        __syncthreads();

        // ---- epilogue: sigma_t * D, max over t, lane-reduce, store partials ----
        float vm[4][2];
        #pragma unroll
        for (int nb = 0; nb < 4; nb++) { vm[nb][0] = -INFINITY; vm[nb][1] = -INFINITY; }
        #pragma unroll
        for (int mb = 0; mb < 4; mb++) {
            const float s0 = smSIG[mh * 64 + mb * 16 + l4];
            const float s1 = smSIG[mh * 64 + mb * 16 + l4 + 8];
            #pragma unroll
            for (int nb = 0; nb < 4; nb++) {
                vm[nb][0] = fmaxf(vm[nb][0], fmaxf(s0 * acc[mb][nb][0], s1 * acc[mb][nb][2]));
                vm[nb][1] = fmaxf(vm[nb][1], fmaxf(s0 * acc[mb][nb][1], s1 * acc[mb][nb][3]));
            }
        }
        #pragma unroll
        for (int nb = 0; nb < 4; nb++) {
            #pragma unroll
            for (int j = 0; j < 2; j++) {
                float v = vm[nb][j];
                v = fmaxf(v, __shfl_xor_sync(0xffffffffu, v, 4));
                v = fmaxf(v, __shfl_xor_sync(0xffffffffu, v, 8));
                v = fmaxf(v, __shfl_xor_sync(0xffffffffu, v, 16));
                vm[nb][j] = v;
            }
        }
        if (l4 == 0) {   // lanes 0..3
            float* gp = g_part + (size_t)tile * 256 + mh * 128;
            #pragma unroll
            for (int nb = 0; nb < 4; nb++) {
                const int o = wo * 32 + nb * 8 + 2 * lane;
                gp[o]     = vm[nb][0];
                gp[o + 1] = vm[nb][1];
            }
        }
        buf ^= 1;
    }
}

__global__ void la_fin(const float* __restrict__ cnnb, float* __restrict__ out) {
    const int i = blockIdx.x * blockDim.x + threadIdx.x;   // b*128 + o
    const int b = i >> 7, o = i & 127;
    float m = -INFINITY;
    #pragma unroll
    for (int j = 0; j < 32; j++)
        m = fmaxf(m, g_part[((size_t)b * 32 + j) * 128 + o]);
    out[i] = tanhf(m + cnnb[o]);
}

extern "C" void kernel_launch(void* const* d_in, const int* in_sizes, int n_in,
                              void* d_out, int out_size) {
    const int*   x    = (const int*)d_in[0];
    const float* emb  = (const float*)d_in[1];
    const float* attw = (const float*)d_in[2];
    const float* attb = (const float*)d_in[3];
    const float* cnnw = (const float*)d_in[4];
    const float* cnnb = (const float*)d_in[5];
    float*       out  = (float*)d_out;

    emb_conv<<<(VOC1 * EE / 8 + 255) / 256, 256>>>(emb);
    cudaFuncSetAttribute(la_main, cudaFuncAttributeMaxDynamicSharedMemorySize, SMEM_DYN);
    la_main<<<GRID, 256, SMEM_DYN>>>(x, attw, attb, cnnw);
    la_fin<<<(BB * OCC) / 256, 256>>>(cnnb, out);
}

// round 17
// speedup vs baseline: 1.0597x; 1.0597x over previous
#include <cuda_runtime.h>
#include <cuda_fp16.h>
#include <math.h>
#include <stdint.h>

#define BB 256
#define TT 2048
#define EE 128
#define OCC 128
#define VOC1 50001
#define NTILES 4096          // BB * TT / 128
#define GRID 296             // 2 CTAs/SM x 148 SMs
#define STH 136              // half-stride of E/W tiles (68 uint32) -> conflict-free frags
#define STU (STH / 2)        // 68

// SMEM byte offsets
#define OFF_E0   0                         // E tile buf0: 128 x 136 halves = 34816
#define OFF_E1   34816
#define OFF_W    69632                     // W tile: 136 x 136 halves = 36992
#define OFF_Q    106624                    // q: 132 rows x 8 floats = 4224
#define OFF_SIG  110848                    // 128 floats
#define OFF_ATT  111360                    // 5 x 128 floats (halo path)
#define SMEM_DYN 113920                    // x2 = 227840 <= 228KB/SM -> occ 2

__device__ unsigned g_max[BB * OCC];                       // zero-init = -NaN sentinel
__device__ __align__(16) __half g_emb16[VOC1 * EE];        // 12.8 MB fp16 table

static __device__ __forceinline__ uint32_t smem_u32(const void* p) {
    uint32_t a;
    asm("{ .reg .u64 t; cvta.to.shared.u64 t, %1; cvt.u32.u64 %0, t; }" : "=r"(a) : "l"(p));
    return a;
}
static __device__ __forceinline__ void cpasync16(uint32_t dst, const void* src) {
    asm volatile("cp.async.cg.shared.global [%0], [%1], 16;" :: "r"(dst), "l"(src));
}
static __device__ __forceinline__ void mma16(float* c,
                                             uint32_t a0, uint32_t a1, uint32_t a2, uint32_t a3,
                                             uint32_t b0, uint32_t b1) {
    asm volatile(
        "mma.sync.aligned.m16n8k16.row.col.f32.f16.f16.f32 "
        "{%0,%1,%2,%3}, {%4,%5,%6,%7}, {%8,%9}, {%0,%1,%2,%3};"
        : "+f"(c[0]), "+f"(c[1]), "+f"(c[2]), "+f"(c[3])
        : "r"(a0), "r"(a1), "r"(a2), "r"(a3), "r"(b0), "r"(b1));
}
// monotone fp32 <-> u32 encoding for atomicMax
static __device__ __forceinline__ unsigned encf(float v) {
    unsigned b = __float_as_uint(v);
    return (b & 0x80000000u) ? ~b : (b | 0x80000000u);
}
static __device__ __forceinline__ float decf(unsigned u) {
    unsigned b = (u & 0x80000000u) ? (u ^ 0x80000000u) : ~u;
    return __uint_as_float(b);
}

// ---- one-shot fp32 -> fp16 table conversion (runs every replay; deterministic) ----
__global__ void emb_conv(const float* __restrict__ emb) {
    const int i = blockIdx.x * blockDim.x + threadIdx.x;   // 8 halves per thread
    if (i >= (VOC1 * EE) / 8) return;
    const float4* s = (const float4*)emb + 2 * i;
    float4 v0 = s[0], v1 = s[1];
    __half2 h0 = __floats2half2_rn(v0.x, v0.y);
    __half2 h1 = __floats2half2_rn(v0.z, v0.w);
    __half2 h2 = __floats2half2_rn(v1.x, v1.y);
    __half2 h3 = __floats2half2_rn(v1.z, v1.w);
    uint4 u;
    u.x = *(uint32_t*)&h0; u.y = *(uint32_t*)&h1;
    u.z = *(uint32_t*)&h2; u.w = *(uint32_t*)&h3;
    ((uint4*)g_emb16)[i] = u;
}

__global__ void __launch_bounds__(256, 2) la_main(
    const int* __restrict__ x, const float* __restrict__ attw,
    const float* __restrict__ attb, const float* __restrict__ cnnw)
{
    extern __shared__ char sm[];
    float* smQ   = (float*)(sm + OFF_Q);     // [u][8], u = 0..131
    float* smSIG = (float*)(sm + OFF_SIG);
    float* smATT = (float*)(sm + OFF_ATT);
    const uint32_t smb = smem_u32(sm);

    const int tid  = threadIdx.x;
    const int lane = tid & 31;
    const int w    = tid >> 5;
    const int wo   = w & 3;          // o-quadrant
    const int mh   = w >> 2;         // t-half
    const int l4   = lane >> 2;
    const int lm   = lane & 3;
    const int r    = tid >> 1;       // row owned in gather (2 threads/row)
    const int h    = tid & 1;        // 64-half segment

    // ---- one-time: W fp16 tile (rows 0..127 = cnn_w, 128..132 = att_w, 133..135 = 0) ----
    {
        const float4* src = (const float4*)(cnnw + r * EE + h * 64);
        uint2* dst = (uint2*)(sm + OFF_W + (r * STH + h * 64) * 2);
        #pragma unroll
        for (int i = 0; i < 16; i++) {
            float4 v = src[i];
            __half2 p01 = __floats2half2_rn(v.x, v.y);
            __half2 p23 = __floats2half2_rn(v.z, v.w);
            uint2 u; u.x = *(uint32_t*)&p01; u.y = *(uint32_t*)&p23;
            dst[i] = u;
        }
    }
    if (tid < 64) {  // 8 extra rows, 8 threads/row, 16 halves each
        const int j = tid >> 3, seg = tid & 7;
        uint2* dst = (uint2*)(sm + OFF_W + ((128 + j) * STH + seg * 16) * 2);
        #pragma unroll
        for (int i = 0; i < 4; i++) {
            float4 v = (j < 5) ? *(const float4*)(attw + j * EE + seg * 16 + 4 * i)
                               : make_float4(0.f, 0.f, 0.f, 0.f);
            __half2 p01 = __floats2half2_rn(v.x, v.y);
            __half2 p23 = __floats2half2_rn(v.z, v.w);
            uint2 u; u.x = *(uint32_t*)&p01; u.y = *(uint32_t*)&p23;
            dst[i] = u;
        }
    }
    for (int i = tid; i < 5 * EE; i += 256) smATT[i] = attw[i];
    const float bias = attb[0];
    __syncthreads();

    const uint32_t* hW = (const uint32_t*)(sm + OFF_W);
    const int aBase = (mh * 64 + l4) * STU + lm;
    const int bBase = (wo * 32 + l4) * STU + lm;
    const int bqBase = (128 + l4) * STU + lm;          // q columns (n = 128..135)
    const uint32_t eDst = (uint32_t)((r * STH + h * 64) * 2);

    // ---- prologue prefetch: first tile -> E0 ----
    {
        const int tile = blockIdx.x;
        const int tok = x[(tile >> 4) * TT + ((tile & 15) << 7) + r];
        const __half* src = g_emb16 + (size_t)tok * EE + h * 64;
        #pragma unroll
        for (int i = 0; i < 8; i++) cpasync16(smb + OFF_E0 + eDst + 16 * i, src + 8 * i);
    }
    asm volatile("cp.async.commit_group;" ::: "memory");

    int buf = 0;
    for (int tile = blockIdx.x; tile < NTILES; tile += GRID) {
        const int b  = tile >> 4;
        const int tb = (tile & 15) << 7;
        const bool has_next = (tile + GRID) < NTILES;

        if (has_next) {
            const int nt = tile + GRID;
            const int tok = x[(nt >> 4) * TT + ((nt & 15) << 7) + r];
            const __half* src = g_emb16 + (size_t)tok * EE + h * 64;
            const uint32_t d = smb + (buf ? OFF_E0 : OFF_E1) + eDst;
            #pragma unroll
            for (int i = 0; i < 8; i++) cpasync16(d + 16 * i, src + 8 * i);
            asm volatile("cp.async.commit_group;" ::: "memory");
            asm volatile("cp.async.wait_group 1;" ::: "memory");
        } else {
            asm volatile("cp.async.wait_group 0;" ::: "memory");
        }
        __syncthreads();   // E[buf] visible

        // ---- halo q (warp 1): rows t-2, t-1, t+128, t+129 -> smQ u = 0,1,130,131 ----
        if (w == 1) {
            const int hh = lane >> 3, seg = lane & 7;
            const int tg = (hh < 2) ? (tb - 2 + hh) : (tb + 126 + hh);
            float vk[5] = {0.f, 0.f, 0.f, 0.f, 0.f};
            if (tg >= 0 && tg < TT) {
                const int tok = x[b * TT + tg];
                const uint4* src = (const uint4*)(g_emb16 + (size_t)tok * EE + seg * 16);
                const float* aw = smATT + seg * 16;
                #pragma unroll
                for (int c8 = 0; c8 < 2; c8++) {
                    uint4 u = src[c8];
                    float f[8];
                    f[0] = __low2float(*(__half2*)&u.x);  f[1] = __high2float(*(__half2*)&u.x);
                    f[2] = __low2float(*(__half2*)&u.y);  f[3] = __high2float(*(__half2*)&u.y);
                    f[4] = __low2float(*(__half2*)&u.z);  f[5] = __high2float(*(__half2*)&u.z);
                    f[6] = __low2float(*(__half2*)&u.w);  f[7] = __high2float(*(__half2*)&u.w);
                    #pragma unroll
                    for (int e = 0; e < 8; e++)
                        #pragma unroll
                        for (int k = 0; k < 5; k++)
                            vk[k] += f[e] * aw[k * EE + c8 * 8 + e];
                }
            }
            #pragma unroll
            for (int k = 0; k < 5; k++) {
                vk[k] += __shfl_xor_sync(0xffffffffu, vk[k], 1);
                vk[k] += __shfl_xor_sync(0xffffffffu, vk[k], 2);
                vk[k] += __shfl_xor_sync(0xffffffffu, vk[k], 4);
            }
            if (seg == 0) {
                const int u = (hh < 2) ? hh : hh + 128;
                #pragma unroll
                for (int k = 0; k < 5; k++) smQ[u * 8 + k] = vk[k];
            }
        }

        // ---- fp16 k-loop: 64t x 32o per warp (+ q columns on wo==3) ----
        const uint32_t* hE = (const uint32_t*)(sm + (buf ? OFF_E1 : OFF_E0));
        float acc[4][4][4];
        float accq[4][4];
        #pragma unroll
        for (int mb = 0; mb < 4; mb++) {
            #pragma unroll
            for (int nb = 0; nb < 4; nb++)
                #pragma unroll
                for (int j = 0; j < 4; j++) acc[mb][nb][j] = 0.f;
            #pragma unroll
            for (int j = 0; j < 4; j++) accq[mb][j] = 0.f;
        }

        #pragma unroll
        for (int kb = 0; kb < 8; kb++) {
            const int kc = kb * 8;
            uint32_t b0[4], b1[4], bq0 = 0, bq1 = 0;
            #pragma unroll
            for (int nb = 0; nb < 4; nb++) {
                b0[nb] = hW[bBase + nb * 8 * STU + kc];
                b1[nb] = hW[bBase + nb * 8 * STU + kc + 4];
            }
            if (wo == 3) {
                bq0 = hW[bqBase + kc];
                bq1 = hW[bqBase + kc + 4];
            }
            #pragma unroll
            for (int mb = 0; mb < 4; mb++) {
                const int ao = aBase + mb * 16 * STU + kc;
                const uint32_t a0 = hE[ao];
                const uint32_t a1 = hE[ao + 8 * STU];
                const uint32_t a2 = hE[ao + 4];
                const uint32_t a3 = hE[ao + 8 * STU + 4];
                #pragma unroll
                for (int nb = 0; nb < 4; nb++)
                    mma16(acc[mb][nb], a0, a1, a2, a3, b0[nb], b1[nb]);
                if (wo == 3)
                    mma16(accq[mb], a0, a1, a2, a3, bq0, bq1);
            }
        }

        // ---- wo==3: scatter q fragments (cols j = 2lm, 2lm+1; keep j < 5) ----
        if (wo == 3 && lm < 3) {
            #pragma unroll
            for (int mb = 0; mb < 4; mb++) {
                const int u0 = mh * 64 + mb * 16 + l4 + 2;
                const int j0 = 2 * lm;
                smQ[u0 * 8 + j0] = accq[mb][0];
                smQ[(u0 + 8) * 8 + j0] = accq[mb][2];
                if (j0 + 1 < 5) {
                    smQ[u0 * 8 + j0 + 1] = accq[mb][1];
                    smQ[(u0 + 8) * 8 + j0 + 1] = accq[mb][3];
                }
            }
        }
        __syncthreads();   // q complete; E[buf] reads done

        // ---- sigmoid: s[t] = sum_k q[t+k][k] ----
        if (tid < 128) {
            float s = smQ[tid * 8]
                    + smQ[(tid + 1) * 8 + 1]
                    + smQ[(tid + 2) * 8 + 2]
                    + smQ[(tid + 3) * 8 + 3]
                    + smQ[(tid + 4) * 8 + 4];
            smSIG[tid] = 1.f / (1.f + __expf(-(s + bias)));
        }
        __syncthreads();

        // ---- epilogue: sigma_t * D, max over t, lane-reduce, atomic-max out ----
        float vm[4][2];
        #pragma unroll
        for (int nb = 0; nb < 4; nb++) { vm[nb][0] = -INFINITY; vm[nb][1] = -INFINITY; }
        #pragma unroll
        for (int mb = 0; mb < 4; mb++) {
            const float s0 = smSIG[mh * 64 + mb * 16 + l4];
            const float s1 = smSIG[mh * 64 + mb * 16 + l4 + 8];
            #pragma unroll
            for (int nb = 0; nb < 4; nb++) {
                vm[nb][0] = fmaxf(vm[nb][0], fmaxf(s0 * acc[mb][nb][0], s1 * acc[mb][nb][2]));
                vm[nb][1] = fmaxf(vm[nb][1], fmaxf(s0 * acc[mb][nb][1], s1 * acc[mb][nb][3]));
            }
        }
        #pragma unroll
        for (int nb = 0; nb < 4; nb++) {
            #pragma unroll
            for (int j = 0; j < 2; j++) {
                float v = vm[nb][j];
                v = fmaxf(v, __shfl_xor_sync(0xffffffffu, v, 4));
                v = fmaxf(v, __shfl_xor_sync(0xffffffffu, v, 8));
                v = fmaxf(v, __shfl_xor_sync(0xffffffffu, v, 16));
                vm[nb][j] = v;
            }
        }
        if (l4 == 0) {   // lanes 0..3
            unsigned* gm = g_max + b * OCC;
            #pragma unroll
            for (int nb = 0; nb < 4; nb++) {
                const int o = wo * 32 + nb * 8 + 2 * lane;
                atomicMax(gm + o,     encf(vm[nb][0]));
                atomicMax(gm + o + 1, encf(vm[nb][1]));
            }
        }
        buf ^= 1;
    }
}

__global__ void la_fin(const float* __restrict__ cnnb, float* __restrict__ out) {
    const int i = blockIdx.x * blockDim.x + threadIdx.x;   // b*128 + o
    const unsigned u = g_max[i];
    g_max[i] = 0u;                       // reset for the next (deterministic) replay
    out[i] = tanhf(decf(u) + cnnb[i & 127]);
}

extern "C" void kernel_launch(void* const* d_in, const int* in_sizes, int n_in,
                              void* d_out, int out_size) {
    const int*   x    = (const int*)d_in[0];
    const float* emb  = (const float*)d_in[1];
    const float* attw = (const float*)d_in[2];
    const float* attb = (const float*)d_in[3];
    const float* cnnw = (const float*)d_in[4];
    const float* cnnb = (const float*)d_in[5];
    float*       out  = (float*)d_out;

    emb_conv<<<(VOC1 * EE / 8 + 255) / 256, 256>>>(emb);
    cudaFuncSetAttribute(la_main, cudaFuncAttributeMaxDynamicSharedMemorySize, SMEM_DYN);
    la_main<<<GRID, 256, SMEM_DYN>>>(x, attw, attb, cnnw);
    la_fin<<<(BB * OCC) / 256, 256>>>(cnnb, out);
}